// round 13
// baseline (speedup 1.0000x reference)
#include <cuda_runtime.h>
#include <cuda_bf16.h>
#include <stdint.h>
#include <math.h>

typedef unsigned int       u32;
typedef unsigned long long u64;

// ---------------- problem constants ----------------
#define B_      2
#define L_      2048
#define DM      1024
#define DI      2048
#define NH      32
#define HD      64
#define DS      64
#define CONVD   2176
#define DPROJ   4256
#define TT      (B_*L_)
#define EPS_    1e-5f

// ---------------- scratch ----------------
__device__ float g_zx [TT*DPROJ];
__device__ float g_xbc[TT*CONVD];
__device__ float g_dt [TT*NH];
__device__ float g_y  [TT*DI];
__device__ float g_x2 [TT*DM];

__device__ __nv_bfloat16 g_h1h[TT*DM],   g_h1l[TT*DM];
__device__ __nv_bfloat16 g_ynh[TT*DI],   g_ynl[TT*DI];
__device__ __nv_bfloat16 g_h2h[TT*DM],   g_h2l[TT*DM];
__device__ __nv_bfloat16 g_glh[TT*4*DM], g_gll[TT*4*DM];
__device__ __nv_bfloat16 g_wih[DPROJ*DM], g_wil[DPROJ*DM];
__device__ __nv_bfloat16 g_woh[DM*DI],    g_wol[DM*DI];
__device__ __nv_bfloat16 g_w1h[4*DM*DM],  g_w1l[4*DM*DM];
__device__ __nv_bfloat16 g_w2h[DM*4*DM],  g_w2l[DM*4*DM];

// ---------------- helpers ----------------
__device__ __forceinline__ float block_reduce_256(float v) {
    static __shared__ float sh[8];
    int tid = threadIdx.x;
    #pragma unroll
    for (int o = 16; o > 0; o >>= 1) v += __shfl_xor_sync(0xffffffffu, v, o);
    __syncthreads();
    if ((tid & 31) == 0) sh[tid >> 5] = v;
    __syncthreads();
    return sh[0]+sh[1]+sh[2]+sh[3]+sh[4]+sh[5]+sh[6]+sh[7];
}

__device__ __forceinline__ float silu_f(float x) {
    return x / (1.f + __expf(-x));
}

__device__ __forceinline__ u32 smem_u32(const void* p) {
    u32 a;
    asm("{ .reg .u64 t; cvta.to.shared.u64 t, %1; cvt.u32.u64 %0, t; }" : "=r"(a) : "l"(p));
    return a;
}

__device__ __forceinline__ void ldsm_x4(u32& r0, u32& r1, u32& r2, u32& r3, u32 addr) {
    asm volatile("ldmatrix.sync.aligned.m8n8.x4.shared.b16 {%0,%1,%2,%3}, [%4];"
                 : "=r"(r0), "=r"(r1), "=r"(r2), "=r"(r3) : "r"(addr));
}

__device__ __forceinline__ void mma_bf16(float* d, u32 a0, u32 a1, u32 a2, u32 a3,
                                         u32 b0, u32 b1) {
    asm volatile(
        "mma.sync.aligned.m16n8k16.row.col.f32.bf16.bf16.f32 "
        "{%0,%1,%2,%3}, {%4,%5,%6,%7}, {%8,%9}, {%0,%1,%2,%3};"
        : "+f"(d[0]), "+f"(d[1]), "+f"(d[2]), "+f"(d[3])
        : "r"(a0), "r"(a1), "r"(a2), "r"(a3), "r"(b0), "r"(b1));
}

__device__ __forceinline__ void split2(float x, float y, u32& hi, u32& lo) {
    __nv_bfloat16 hx = __float2bfloat16(x);
    __nv_bfloat16 hy = __float2bfloat16(y);
    float rx = x - __bfloat162float(hx);
    float ry = y - __bfloat162float(hy);
    __nv_bfloat16 lx = __float2bfloat16(rx);
    __nv_bfloat16 ly = __float2bfloat16(ry);
    hi = (u32)__bfloat16_as_ushort(hx) | ((u32)__bfloat16_as_ushort(hy) << 16);
    lo = (u32)__bfloat16_as_ushort(lx) | ((u32)__bfloat16_as_ushort(ly) << 16);
}

__device__ __forceinline__ void cp16(u32 smem, const void* g) {
    asm volatile("cp.async.cg.shared.global [%0], [%1], 16;" :: "r"(smem), "l"(g) : "memory");
}
#define CP_COMMIT() asm volatile("cp.async.commit_group;" ::: "memory")

// ---------------- split-bf16 HMMA GEMM: C = A @ B^T ----------------
// A,B pre-split hi/lo bf16, row-major [M,K]/[N,K].
// epi: 0 C fp32; 1 +res; 2 bias+gelu -> Chi/Clo bf16; 3 bias+res
#define ROWB   80
#define BUF_LO 10240u
#define BUF_BH 20480u
#define STAGE_SZ 40960u
#define NSTAGE 4
#define SMEM_MM (4u * STAGE_SZ)   /* 163840 */

__global__ void __launch_bounds__(256)
mm_kernel(const __nv_bfloat16* __restrict__ Ahi, const __nv_bfloat16* __restrict__ Alo,
          const __nv_bfloat16* __restrict__ Bhi, const __nv_bfloat16* __restrict__ Blo,
          const float* __restrict__ bias, const float* __restrict__ res,
          float* __restrict__ C, __nv_bfloat16* __restrict__ Chi,
          __nv_bfloat16* __restrict__ Clo,
          int M, int N, int K, int epi) {
    extern __shared__ char smc[];
    u32 sb = smem_u32(smc);

    int tid = threadIdx.x;
    int wid = tid >> 5, t = tid & 31;
    int bx = blockIdx.x, by = blockIdx.y;
    int wm = wid >> 2, wn = wid & 3;      // warp tile m64 x n32

    float acc[4][4][4];
    #pragma unroll
    for (int i = 0; i < 4; i++)
        #pragma unroll
        for (int j = 0; j < 4; j++)
            #pragma unroll
            for (int k = 0; k < 4; k++) acc[i][j][k] = 0.f;

    const int nc = K >> 5;

    // each thread owns 32B (two 16B chunks) of one row per buffer
    int lr = tid >> 1;                 // row 0..127
    int ch = (tid & 1) * 32;           // byte offset within 64B k-slice
    int ga = by * 128 + lr;
    int gb = bx * 128 + lr; if (gb > N - 1) gb = N - 1;
    const char* pAh = (const char*)(Ahi + (size_t)ga * K) + ch;
    const char* pAl = (const char*)(Alo + (size_t)ga * K) + ch;
    const char* pBh = (const char*)(Bhi + (size_t)gb * K) + ch;
    const char* pBl = (const char*)(Blo + (size_t)gb * K) + ch;
    u32 sO = (u32)lr * ROWB + (u32)ch;

    auto issue = [&](int c, int s) {
        u32 base = sb + (u32)s * STAGE_SZ + sO;
        size_t go = (size_t)(c << 6);      // c*32 bf16 = c*64 bytes
        cp16(base,               pAh + go);
        cp16(base + 16,          pAh + go + 16);
        cp16(base + BUF_LO,      pAl + go);
        cp16(base + BUF_LO + 16, pAl + go + 16);
        cp16(base + BUF_BH,               pBh + go);
        cp16(base + BUF_BH + 16,          pBh + go + 16);
        cp16(base + BUF_BH + BUF_LO,      pBl + go);
        cp16(base + BUF_BH + BUF_LO + 16, pBl + go + 16);
    };

    // ldmatrix addressing (proven R7/R12)
    u32 arow = (u32)(wm * 64 + (t & 15));
    u32 acol = (u32)((t >> 4) << 4);
    u32 brow = (u32)(wn * 32 + (t & 7) + ((t >> 4) << 3));
    u32 bcol = (u32)(((t >> 3) & 1) << 4);

    auto compute = [&](int s) {
        u32 base = sb + (u32)s * STAGE_SZ;
        #pragma unroll
        for (int ks = 0; ks < 2; ks++) {
            u32 kb = (u32)(ks * 32);
            u32 ah[4][4], al[4][4], bh[2][4], bl[2][4];
            #pragma unroll
            for (int mi = 0; mi < 4; mi++) {
                u32 ad = base + (arow + mi * 16) * ROWB + kb + acol;
                ldsm_x4(ah[mi][0], ah[mi][1], ah[mi][2], ah[mi][3], ad);
                ldsm_x4(al[mi][0], al[mi][1], al[mi][2], al[mi][3], ad + BUF_LO);
            }
            #pragma unroll
            for (int nj = 0; nj < 2; nj++) {
                u32 bd = base + BUF_BH + (brow + nj * 16) * ROWB + kb + bcol;
                ldsm_x4(bh[nj][0], bh[nj][1], bh[nj][2], bh[nj][3], bd);
                ldsm_x4(bl[nj][0], bl[nj][1], bl[nj][2], bl[nj][3], bd + BUF_LO);
            }
            #pragma unroll
            for (int mi = 0; mi < 4; mi++) {
                #pragma unroll
                for (int nj = 0; nj < 4; nj++) {
                    u32 b0h = bh[nj >> 1][(nj & 1) * 2], b1h = bh[nj >> 1][(nj & 1) * 2 + 1];
                    u32 b0l = bl[nj >> 1][(nj & 1) * 2], b1l = bl[nj >> 1][(nj & 1) * 2 + 1];
                    mma_bf16(acc[mi][nj], ah[mi][0], ah[mi][1], ah[mi][2], ah[mi][3], b0h, b1h);
                    mma_bf16(acc[mi][nj], ah[mi][0], ah[mi][1], ah[mi][2], ah[mi][3], b0l, b1l);
                    mma_bf16(acc[mi][nj], al[mi][0], al[mi][1], al[mi][2], al[mi][3], b0h, b1h);
                }
            }
        }
    };

    // ---- 4-stage cp.async pipeline, one barrier per iteration ----
    issue(0, 0); CP_COMMIT();
    issue(1, 1); CP_COMMIT();
    issue(2, 2); CP_COMMIT();
    for (int c = 0; c < nc; c++) {
        asm volatile("cp.async.wait_group 2;" ::: "memory");
        __syncthreads();
        compute(c & 3);
        if (c + 3 < nc) issue(c + 3, (c + 3) & 3);
        CP_COMMIT();
    }

    // ---- epilogue ----
    int gid = t >> 2, tig = t & 3;
    #pragma unroll
    for (int mi = 0; mi < 4; mi++) {
        int gm0 = by * 128 + wm * 64 + mi * 16 + gid;
        #pragma unroll
        for (int nj = 0; nj < 4; nj++) {
            int gn = bx * 128 + wn * 32 + nj * 8 + tig * 2;
            if (gn >= N) continue;
            #pragma unroll
            for (int h = 0; h < 2; h++) {
                int gr = gm0 + h * 8;
                float vx = acc[mi][nj][h * 2 + 0];
                float vy = acc[mi][nj][h * 2 + 1];
                if (epi == 2 || epi == 3) {
                    float2 bv = *(const float2*)(bias + gn);
                    vx += bv.x; vy += bv.y;
                }
                if (epi == 2) {
                    vx = 0.5f * vx * (1.f + erff(vx * 0.70710678118654752f));
                    vy = 0.5f * vy * (1.f + erff(vy * 0.70710678118654752f));
                    u32 hp, lp;
                    split2(vx, vy, hp, lp);
                    *(u32*)(Chi + (size_t)gr * N + gn) = hp;
                    *(u32*)(Clo + (size_t)gr * N + gn) = lp;
                } else {
                    if (epi == 1 || epi == 3) {
                        float2 rv = *(const float2*)(res + (size_t)gr * N + gn);
                        vx += rv.x; vy += rv.y;
                    }
                    float2 o; o.x = vx; o.y = vy;
                    *(float2*)(C + (size_t)gr * N + gn) = o;
                }
            }
        }
    }
}

// ---------------- weight split ----------------
__global__ void wsplit_kernel(const float* __restrict__ in, __nv_bfloat16* __restrict__ hi,
                              __nv_bfloat16* __restrict__ lo, int n4) {
    int i = blockIdx.x * blockDim.x + threadIdx.x;
    if (i >= n4) return;
    float4 v = ((const float4*)in)[i];
    u32 h0, l0, h1, l1;
    split2(v.x, v.y, h0, l0);
    split2(v.z, v.w, h1, l1);
    ((uint2*)hi)[i] = make_uint2(h0, h1);
    ((uint2*)lo)[i] = make_uint2(l0, l1);
}

// ---------------- LayerNorm -> hi/lo bf16 ----------------
__global__ void ln_bf_kernel(const float* __restrict__ in, const float* __restrict__ w,
                             const float* __restrict__ b,
                             __nv_bfloat16* __restrict__ hi, __nv_bfloat16* __restrict__ lo) {
    int row = blockIdx.x, tid = threadIdx.x;
    float4 v = ((const float4*)(in + (size_t)row * DM))[tid];
    float s  = v.x + v.y + v.z + v.w;
    float sq = v.x*v.x + v.y*v.y + v.z*v.z + v.w*v.w;
    float tot   = block_reduce_256(s);
    float totsq = block_reduce_256(sq);
    float mean = tot * (1.f / DM);
    float var  = totsq * (1.f / DM) - mean * mean;
    float inv  = rsqrtf(var + EPS_);
    float4 wv = ((const float4*)w)[tid];
    float4 bv = ((const float4*)b)[tid];
    float4 o;
    o.x = (v.x - mean) * inv * wv.x + bv.x;
    o.y = (v.y - mean) * inv * wv.y + bv.y;
    o.z = (v.z - mean) * inv * wv.z + bv.z;
    o.w = (v.w - mean) * inv * wv.w + bv.w;
    u32 h0, l0, h1, l1;
    split2(o.x, o.y, h0, l0);
    split2(o.z, o.w, h1, l1);
    ((uint2*)(hi + (size_t)row * DM))[tid] = make_uint2(h0, h1);
    ((uint2*)(lo + (size_t)row * DM))[tid] = make_uint2(l0, l1);
}

// ---------------- conv4 + silu ----------------
__global__ void conv_kernel(const float* __restrict__ zx, const float* __restrict__ w,
                            const float* __restrict__ bias, float* __restrict__ out) {
    int idx = blockIdx.x * blockDim.x + threadIdx.x;
    if (idx >= TT * CONVD) return;
    int c = idx % CONVD;
    int tt = idx / CONVD;
    int l = tt % L_;
    float acc = bias[c];
    #pragma unroll
    for (int k = 0; k < 4; k++) {
        int ls = l - 3 + k;
        if (ls >= 0)
            acc += zx[(size_t)(tt - 3 + k) * DPROJ + DI + c] * w[c * 4 + k];
    }
    out[idx] = silu_f(acc);
}

// ---------------- dt softplus ----------------
__global__ void dt_kernel(const float* __restrict__ zx, const float* __restrict__ dtb,
                          float* __restrict__ dt) {
    int idx = blockIdx.x * blockDim.x + threadIdx.x;
    if (idx >= TT * NH) return;
    int h = idx % NH;
    float v = zx[(size_t)(idx / NH) * DPROJ + DI + CONVD + h] + dtb[h];
    dt[idx] = (v > 20.f) ? v : log1pf(expf(v));
}

// ---------------- selective scan ----------------
#define CH 8
__global__ void __launch_bounds__(128)
scan_kernel(const float* __restrict__ xbc, const float* __restrict__ dtg,
            const float* __restrict__ A_log, const float* __restrict__ Dp,
            float* __restrict__ y) {
    int blk  = blockIdx.x;
    int half = blk & 1;
    int bh   = blk >> 1;
    int b = bh / NH, h = bh % NH;
    int tid = threadIdx.x;
    int pl  = tid >> 2;
    int q   = tid & 3;
    int p   = half * 32 + pl;

    float Aneg = -expf(A_log[h]);
    float Dh   = Dp[h];

    __shared__ float sB[CH][DS], sC[CH][DS], sx[CH][32], sdt[CH];

    float hreg[16];
    #pragma unroll
    for (int i = 0; i < 16; i++) hreg[i] = 0.f;

    const float* base = xbc + (size_t)b * L_ * CONVD;

    for (int t0 = 0; t0 < L_; t0 += CH) {
        #pragma unroll
        for (int tt = 0; tt < CH; tt++) {
            int tq = t0 + tt;
            const float* rowp = base + (size_t)tq * CONVD;
            if (tid < 64) sB[tt][tid]      = rowp[DI + tid];
            else          sC[tt][tid - 64] = rowp[DI + DS + (tid - 64)];
        }
        #pragma unroll
        for (int tt = 0; tt < CH; tt++) {
            int tq = t0 + tt;
            if (tid < 32)       sx[tt][tid] = base[(size_t)tq * CONVD + h * HD + half * 32 + tid];
            else if (tid == 32) sdt[tt]     = dtg[((size_t)b * L_ + tq) * NH + h];
        }
        __syncthreads();

        #pragma unroll
        for (int tt = 0; tt < CH; tt++) {
            float dtv = sdt[tt];
            float dA  = expf(dtv * Aneg);
            float xv  = sx[tt][pl];
            float cb  = dtv * xv;
            float acc = 0.f;
            #pragma unroll
            for (int i = 0; i < 16; i++) {
                int n = q * 16 + i;
                float hv = hreg[i] * dA + cb * sB[tt][n];
                hreg[i] = hv;
                acc += hv * sC[tt][n];
            }
            acc += __shfl_xor_sync(0xffffffffu, acc, 1);
            acc += __shfl_xor_sync(0xffffffffu, acc, 2);
            if (q == 0) {
                int tq = t0 + tt;
                y[((size_t)b * L_ + tq) * DI + h * HD + p] = acc + Dh * xv;
            }
        }
        __syncthreads();
    }
}

// ---------------- gated RMSNorm -> hi/lo bf16 ----------------
__global__ void rmsnorm_bf_kernel(const float* __restrict__ y, const float* __restrict__ zx,
                                  const float* __restrict__ nw,
                                  __nv_bfloat16* __restrict__ hi, __nv_bfloat16* __restrict__ lo) {
    int row = blockIdx.x, tid = threadIdx.x;
    const float* yr = y  + (size_t)row * DI;
    const float* zr = zx + (size_t)row * DPROJ;
    int c0 = tid * 8;
    float4 y0 = *(const float4*)(yr + c0);
    float4 y1 = *(const float4*)(yr + c0 + 4);
    float4 z0 = *(const float4*)(zr + c0);
    float4 z1 = *(const float4*)(zr + c0 + 4);
    float v[8];
    v[0] = y0.x * silu_f(z0.x); v[1] = y0.y * silu_f(z0.y);
    v[2] = y0.z * silu_f(z0.z); v[3] = y0.w * silu_f(z0.w);
    v[4] = y1.x * silu_f(z1.x); v[5] = y1.y * silu_f(z1.y);
    v[6] = y1.z * silu_f(z1.z); v[7] = y1.w * silu_f(z1.w);
    float sq = 0.f;
    #pragma unroll
    for (int i = 0; i < 8; i++) sq += v[i] * v[i];
    float tot = block_reduce_256(sq);
    float scale = rsqrtf(tot * (1.f / DI) + EPS_);
    float4 w0 = *(const float4*)(nw + c0);
    float4 w1 = *(const float4*)(nw + c0 + 4);
    float o[8];
    o[0] = v[0]*scale*w0.x; o[1] = v[1]*scale*w0.y;
    o[2] = v[2]*scale*w0.z; o[3] = v[3]*scale*w0.w;
    o[4] = v[4]*scale*w1.x; o[5] = v[5]*scale*w1.y;
    o[6] = v[6]*scale*w1.z; o[7] = v[7]*scale*w1.w;
    u32 hp[4], lp[4];
    #pragma unroll
    for (int i = 0; i < 4; i++) split2(o[i*2], o[i*2+1], hp[i], lp[i]);
    ((uint2*)(hi + (size_t)row * DI + c0))[0] = make_uint2(hp[0], hp[1]);
    ((uint2*)(hi + (size_t)row * DI + c0))[1] = make_uint2(hp[2], hp[3]);
    ((uint2*)(lo + (size_t)row * DI + c0))[0] = make_uint2(lp[0], lp[1]);
    ((uint2*)(lo + (size_t)row * DI + c0))[1] = make_uint2(lp[2], lp[3]);
}

// ---------------- launch ----------------
extern "C" void kernel_launch(void* const* d_in, const int* in_sizes, int n_in,
                              void* d_out, int out_size) {
    const float* x          = (const float*)d_in[0];
    const float* ln1_w      = (const float*)d_in[1];
    const float* ln1_b      = (const float*)d_in[2];
    const float* in_proj_w  = (const float*)d_in[3];
    const float* conv_w     = (const float*)d_in[4];
    const float* conv_b     = (const float*)d_in[5];
    const float* dt_bias    = (const float*)d_in[6];
    const float* A_log      = (const float*)d_in[7];
    const float* Dv         = (const float*)d_in[8];
    const float* norm_w     = (const float*)d_in[9];
    const float* out_proj_w = (const float*)d_in[10];
    const float* ln2_w      = (const float*)d_in[11];
    const float* ln2_b      = (const float*)d_in[12];
    const float* mlp_w1     = (const float*)d_in[13];
    const float* mlp_b1     = (const float*)d_in[14];
    const float* mlp_w2     = (const float*)d_in[15];
    const float* mlp_b2     = (const float*)d_in[16];
    float* out = (float*)d_out;

    static float *p_zx = 0, *p_xbc = 0, *p_dt = 0, *p_y = 0, *p_x2 = 0;
    static __nv_bfloat16 *p_h1h = 0, *p_h1l, *p_ynh, *p_ynl, *p_h2h, *p_h2l, *p_glh, *p_gll;
    static __nv_bfloat16 *p_wih, *p_wil, *p_woh, *p_wol, *p_w1h, *p_w1l, *p_w2h, *p_w2l;
    if (p_zx == 0) {
        cudaGetSymbolAddress((void**)&p_zx,  g_zx);
        cudaGetSymbolAddress((void**)&p_xbc, g_xbc);
        cudaGetSymbolAddress((void**)&p_dt,  g_dt);
        cudaGetSymbolAddress((void**)&p_y,   g_y);
        cudaGetSymbolAddress((void**)&p_x2,  g_x2);
        cudaGetSymbolAddress((void**)&p_h1h, g_h1h);
        cudaGetSymbolAddress((void**)&p_h1l, g_h1l);
        cudaGetSymbolAddress((void**)&p_ynh, g_ynh);
        cudaGetSymbolAddress((void**)&p_ynl, g_ynl);
        cudaGetSymbolAddress((void**)&p_h2h, g_h2h);
        cudaGetSymbolAddress((void**)&p_h2l, g_h2l);
        cudaGetSymbolAddress((void**)&p_glh, g_glh);
        cudaGetSymbolAddress((void**)&p_gll, g_gll);
        cudaGetSymbolAddress((void**)&p_wih, g_wih);
        cudaGetSymbolAddress((void**)&p_wil, g_wil);
        cudaGetSymbolAddress((void**)&p_woh, g_woh);
        cudaGetSymbolAddress((void**)&p_wol, g_wol);
        cudaGetSymbolAddress((void**)&p_w1h, g_w1h);
        cudaGetSymbolAddress((void**)&p_w1l, g_w1l);
        cudaGetSymbolAddress((void**)&p_w2h, g_w2h);
        cudaGetSymbolAddress((void**)&p_w2l, g_w2l);
        cudaFuncSetAttribute(mm_kernel, cudaFuncAttributeMaxDynamicSharedMemorySize,
                             (int)SMEM_MM);
    }

    dim3 blk256(256, 1, 1);

    // weight splits (memory bound)
    wsplit_kernel<<<(DPROJ * DM / 4 + 255) / 256, 256>>>(in_proj_w, p_wih, p_wil, DPROJ * DM / 4);
    wsplit_kernel<<<(DM * DI / 4 + 255) / 256, 256>>>(out_proj_w, p_woh, p_wol, DM * DI / 4);
    wsplit_kernel<<<(4 * DM * DM / 4 + 255) / 256, 256>>>(mlp_w1, p_w1h, p_w1l, 4 * DM * DM / 4);
    wsplit_kernel<<<(DM * 4 * DM / 4 + 255) / 256, 256>>>(mlp_w2, p_w2h, p_w2l, DM * 4 * DM / 4);

    // 1) LN1 -> hi/lo
    ln_bf_kernel<<<TT, 256>>>(x, ln1_w, ln1_b, p_h1h, p_h1l);

    // 2) in_proj
    dim3 g1((DPROJ + 127) / 128, TT / 128, 1);
    mm_kernel<<<g1, blk256, SMEM_MM>>>(p_h1h, p_h1l, p_wih, p_wil,
                                       (const float*)0, (const float*)0,
                                       p_zx, (__nv_bfloat16*)0, (__nv_bfloat16*)0,
                                       TT, DPROJ, DM, 0);

    // 3) conv + dt
    conv_kernel<<<(TT * CONVD + 255) / 256, 256>>>(p_zx, conv_w, conv_b, p_xbc);
    dt_kernel<<<(TT * NH + 255) / 256, 256>>>(p_zx, dt_bias, p_dt);

    // 4) scan
    scan_kernel<<<B_ * NH * 2, 128>>>(p_xbc, p_dt, A_log, Dv, p_y);

    // 5) gated rmsnorm -> hi/lo
    rmsnorm_bf_kernel<<<TT, 256>>>(p_y, p_zx, norm_w, p_ynh, p_ynl);

    // 6) out_proj + residual
    dim3 g2(DM / 128, TT / 128, 1);
    mm_kernel<<<g2, blk256, SMEM_MM>>>(p_ynh, p_ynl, p_woh, p_wol,
                                       (const float*)0, x,
                                       p_x2, (__nv_bfloat16*)0, (__nv_bfloat16*)0,
                                       TT, DM, DI, 1);

    // 7) LN2 -> hi/lo
    ln_bf_kernel<<<TT, 256>>>(p_x2, ln2_w, ln2_b, p_h2h, p_h2l);

    // 8) mlp1 + bias + gelu -> hi/lo
    dim3 g3(4 * DM / 128, TT / 128, 1);
    mm_kernel<<<g3, blk256, SMEM_MM>>>(p_h2h, p_h2l, p_w1h, p_w1l,
                                       mlp_b1, (const float*)0,
                                       (float*)0, p_glh, p_gll,
                                       TT, 4 * DM, DM, 2);

    // 9) mlp2 + bias + residual -> out
    dim3 g4(DM / 128, TT / 128, 1);
    mm_kernel<<<g4, blk256, SMEM_MM>>>(p_glh, p_gll, p_w2h, p_w2l,
                                       mlp_b2, p_x2,
                                       out, (__nv_bfloat16*)0, (__nv_bfloat16*)0,
                                       TT, DM, 4 * DM, 3);
}

// round 14
// speedup vs baseline: 1.5421x; 1.5421x over previous
#include <cuda_runtime.h>
#include <cuda_bf16.h>
#include <stdint.h>
#include <math.h>

typedef unsigned int       u32;
typedef unsigned long long u64;

// ---------------- problem constants ----------------
#define B_      2
#define L_      2048
#define DM      1024
#define DI      2048
#define NH      32
#define HD      64
#define DS      64
#define CONVD   2176
#define DPROJ   4256
#define TT      (B_*L_)
#define EPS_    1e-5f

// ---------------- scratch ----------------
__device__ float g_zx [TT*DPROJ];
__device__ float g_xbc[TT*CONVD];
__device__ float g_dt [TT*NH];
__device__ float g_y  [TT*DI];
__device__ float g_x2 [TT*DM];

__device__ __nv_bfloat16 g_h1h[TT*DM],   g_h1l[TT*DM];
__device__ __nv_bfloat16 g_ynh[TT*DI],   g_ynl[TT*DI];
__device__ __nv_bfloat16 g_h2h[TT*DM],   g_h2l[TT*DM];
__device__ __nv_bfloat16 g_glh[TT*4*DM], g_gll[TT*4*DM];
__device__ __nv_bfloat16 g_wih[DPROJ*DM], g_wil[DPROJ*DM];
__device__ __nv_bfloat16 g_woh[DM*DI],    g_wol[DM*DI];
__device__ __nv_bfloat16 g_w1h[4*DM*DM],  g_w1l[4*DM*DM];
__device__ __nv_bfloat16 g_w2h[DM*4*DM],  g_w2l[DM*4*DM];

// ---------------- helpers ----------------
__device__ __forceinline__ float block_reduce_256(float v) {
    static __shared__ float sh[8];
    int tid = threadIdx.x;
    #pragma unroll
    for (int o = 16; o > 0; o >>= 1) v += __shfl_xor_sync(0xffffffffu, v, o);
    __syncthreads();
    if ((tid & 31) == 0) sh[tid >> 5] = v;
    __syncthreads();
    return sh[0]+sh[1]+sh[2]+sh[3]+sh[4]+sh[5]+sh[6]+sh[7];
}

__device__ __forceinline__ float silu_f(float x) {
    return x / (1.f + __expf(-x));
}

__device__ __forceinline__ u32 smem_u32(const void* p) {
    u32 a;
    asm("{ .reg .u64 t; cvta.to.shared.u64 t, %1; cvt.u32.u64 %0, t; }" : "=r"(a) : "l"(p));
    return a;
}

__device__ __forceinline__ void ldsm_x4(u32& r0, u32& r1, u32& r2, u32& r3, u32 addr) {
    asm volatile("ldmatrix.sync.aligned.m8n8.x4.shared.b16 {%0,%1,%2,%3}, [%4];"
                 : "=r"(r0), "=r"(r1), "=r"(r2), "=r"(r3) : "r"(addr));
}

__device__ __forceinline__ void sts128(u32 addr, uint4 v) {
    asm volatile("st.shared.v4.b32 [%0], {%1,%2,%3,%4};"
                 :: "r"(addr), "r"(v.x), "r"(v.y), "r"(v.z), "r"(v.w) : "memory");
}

__device__ __forceinline__ void mma_bf16(float* d, u32 a0, u32 a1, u32 a2, u32 a3,
                                         u32 b0, u32 b1) {
    asm volatile(
        "mma.sync.aligned.m16n8k16.row.col.f32.bf16.bf16.f32 "
        "{%0,%1,%2,%3}, {%4,%5,%6,%7}, {%8,%9}, {%0,%1,%2,%3};"
        : "+f"(d[0]), "+f"(d[1]), "+f"(d[2]), "+f"(d[3])
        : "r"(a0), "r"(a1), "r"(a2), "r"(a3), "r"(b0), "r"(b1));
}

__device__ __forceinline__ void split2(float x, float y, u32& hi, u32& lo) {
    __nv_bfloat16 hx = __float2bfloat16(x);
    __nv_bfloat16 hy = __float2bfloat16(y);
    float rx = x - __bfloat162float(hx);
    float ry = y - __bfloat162float(hy);
    __nv_bfloat16 lx = __float2bfloat16(rx);
    __nv_bfloat16 ly = __float2bfloat16(ry);
    hi = (u32)__bfloat16_as_ushort(hx) | ((u32)__bfloat16_as_ushort(hy) << 16);
    lo = (u32)__bfloat16_as_ushort(lx) | ((u32)__bfloat16_as_ushort(ly) << 16);
}

// ---------------- split-bf16 HMMA GEMM: C = A @ B^T ----------------
// 512 threads, 16 warps (4x4), warp tile m32 x n32. 3-stage smem ring,
// register-staged LDG->STS (cp.async empirically slower on this setup).
// epi: 0 C fp32; 1 +res; 2 bias+gelu -> Chi/Clo bf16; 3 bias+res
#define ROWB   80
#define BUF_LO 10240u
#define BUF_BH 20480u
#define STAGE_SZ 40960u
#define SMEM_MM (3u * STAGE_SZ)   /* 122880 */

__global__ void __launch_bounds__(512)
mm_kernel(const __nv_bfloat16* __restrict__ Ahi, const __nv_bfloat16* __restrict__ Alo,
          const __nv_bfloat16* __restrict__ Bhi, const __nv_bfloat16* __restrict__ Blo,
          const float* __restrict__ bias, const float* __restrict__ res,
          float* __restrict__ C, __nv_bfloat16* __restrict__ Chi,
          __nv_bfloat16* __restrict__ Clo,
          int M, int N, int K, int epi) {
    extern __shared__ char smc[];
    u32 sb = smem_u32(smc);

    int tid = threadIdx.x;
    int wid = tid >> 5, t = tid & 31;
    int bx = blockIdx.x, by = blockIdx.y;
    int wm = wid & 3, wn = wid >> 2;      // 4x4 warp grid, warp tile m32 x n32

    float acc[2][4][4];
    #pragma unroll
    for (int i = 0; i < 2; i++)
        #pragma unroll
        for (int j = 0; j < 4; j++)
            #pragma unroll
            for (int k = 0; k < 4; k++) acc[i][j][k] = 0.f;

    const int nc = K >> 5;

    // each thread owns one 16B chunk of one row per buffer
    int lr = tid >> 2;                 // row 0..127
    int ch = (tid & 3) * 16;           // byte offset within 64B k-slice
    int ga = by * 128 + lr;
    int gb = bx * 128 + lr; if (gb > N - 1) gb = N - 1;
    const char* pAh = (const char*)(Ahi + (size_t)ga * K) + ch;
    const char* pAl = (const char*)(Alo + (size_t)ga * K) + ch;
    const char* pBh = (const char*)(Bhi + (size_t)gb * K) + ch;
    const char* pBl = (const char*)(Blo + (size_t)gb * K) + ch;
    u32 sO = (u32)lr * ROWB + (u32)ch;

    uint4 rg[4];
    auto load_regs = [&](int c) {
        size_t go = (size_t)(c << 6);       // c*32 bf16 = c*64 bytes
        rg[0] = *(const uint4*)(pAh + go);
        rg[1] = *(const uint4*)(pAl + go);
        rg[2] = *(const uint4*)(pBh + go);
        rg[3] = *(const uint4*)(pBl + go);
    };
    auto store_smem = [&](int s) {
        u32 base = sb + (u32)s * STAGE_SZ + sO;
        sts128(base,                   rg[0]);
        sts128(base + BUF_LO,          rg[1]);
        sts128(base + BUF_BH,          rg[2]);
        sts128(base + BUF_BH + BUF_LO, rg[3]);
    };

    // ldmatrix addressing (same scheme as R7/R12, warp tiles rescaled)
    u32 arow = (u32)(wm * 32 + (t & 15));
    u32 acol = (u32)((t >> 4) << 4);
    u32 brow = (u32)(wn * 32 + (t & 7) + ((t >> 4) << 3));
    u32 bcol = (u32)(((t >> 3) & 1) << 4);

    auto compute = [&](int s) {
        u32 base = sb + (u32)s * STAGE_SZ;
        #pragma unroll
        for (int ks = 0; ks < 2; ks++) {
            u32 kb = (u32)(ks * 32);
            u32 ah[2][4], al[2][4], bh[2][4], bl[2][4];
            #pragma unroll
            for (int mi = 0; mi < 2; mi++) {
                u32 ad = base + (arow + mi * 16) * ROWB + kb + acol;
                ldsm_x4(ah[mi][0], ah[mi][1], ah[mi][2], ah[mi][3], ad);
                ldsm_x4(al[mi][0], al[mi][1], al[mi][2], al[mi][3], ad + BUF_LO);
            }
            #pragma unroll
            for (int nj = 0; nj < 2; nj++) {
                u32 bd = base + BUF_BH + (brow + nj * 16) * ROWB + kb + bcol;
                ldsm_x4(bh[nj][0], bh[nj][1], bh[nj][2], bh[nj][3], bd);
                ldsm_x4(bl[nj][0], bl[nj][1], bl[nj][2], bl[nj][3], bd + BUF_LO);
            }
            #pragma unroll
            for (int mi = 0; mi < 2; mi++) {
                #pragma unroll
                for (int nj = 0; nj < 4; nj++) {
                    u32 b0h = bh[nj >> 1][(nj & 1) * 2], b1h = bh[nj >> 1][(nj & 1) * 2 + 1];
                    u32 b0l = bl[nj >> 1][(nj & 1) * 2], b1l = bl[nj >> 1][(nj & 1) * 2 + 1];
                    mma_bf16(acc[mi][nj], ah[mi][0], ah[mi][1], ah[mi][2], ah[mi][3], b0h, b1h);
                    mma_bf16(acc[mi][nj], ah[mi][0], ah[mi][1], ah[mi][2], ah[mi][3], b0l, b1l);
                    mma_bf16(acc[mi][nj], al[mi][0], al[mi][1], al[mi][2], al[mi][3], b0h, b1h);
                }
            }
        }
    };

    // ---- 3-stage ring, register staging, ONE barrier per iteration ----
    load_regs(0); store_smem(0);
    load_regs(1); store_smem(1);
    __syncthreads();
    int s_cur = 0, s_next = 2;
    for (int c = 0; c < nc; c++) {
        bool pre = (c + 2 < nc);
        if (pre) load_regs(c + 2);
        compute(s_cur);
        if (pre) store_smem(s_next);
        __syncthreads();
        s_cur  = (s_cur  == 2) ? 0 : s_cur  + 1;
        s_next = (s_next == 2) ? 0 : s_next + 1;
    }

    // ---- epilogue ----
    int gid = t >> 2, tig = t & 3;
    #pragma unroll
    for (int mi = 0; mi < 2; mi++) {
        int gm0 = by * 128 + wm * 32 + mi * 16 + gid;
        #pragma unroll
        for (int nj = 0; nj < 4; nj++) {
            int gn = bx * 128 + wn * 32 + nj * 8 + tig * 2;
            if (gn >= N) continue;
            #pragma unroll
            for (int h = 0; h < 2; h++) {
                int gr = gm0 + h * 8;
                float vx = acc[mi][nj][h * 2 + 0];
                float vy = acc[mi][nj][h * 2 + 1];
                if (epi == 2 || epi == 3) {
                    float2 bv = *(const float2*)(bias + gn);
                    vx += bv.x; vy += bv.y;
                }
                if (epi == 2) {
                    vx = 0.5f * vx * (1.f + erff(vx * 0.70710678118654752f));
                    vy = 0.5f * vy * (1.f + erff(vy * 0.70710678118654752f));
                    u32 hp, lp;
                    split2(vx, vy, hp, lp);
                    *(u32*)(Chi + (size_t)gr * N + gn) = hp;
                    *(u32*)(Clo + (size_t)gr * N + gn) = lp;
                } else {
                    if (epi == 1 || epi == 3) {
                        float2 rv = *(const float2*)(res + (size_t)gr * N + gn);
                        vx += rv.x; vy += rv.y;
                    }
                    float2 o; o.x = vx; o.y = vy;
                    *(float2*)(C + (size_t)gr * N + gn) = o;
                }
            }
        }
    }
}

// ---------------- weight split ----------------
__global__ void wsplit_kernel(const float* __restrict__ in, __nv_bfloat16* __restrict__ hi,
                              __nv_bfloat16* __restrict__ lo, int n4) {
    int i = blockIdx.x * blockDim.x + threadIdx.x;
    if (i >= n4) return;
    float4 v = ((const float4*)in)[i];
    u32 h0, l0, h1, l1;
    split2(v.x, v.y, h0, l0);
    split2(v.z, v.w, h1, l1);
    ((uint2*)hi)[i] = make_uint2(h0, h1);
    ((uint2*)lo)[i] = make_uint2(l0, l1);
}

// ---------------- LayerNorm -> hi/lo bf16 ----------------
__global__ void ln_bf_kernel(const float* __restrict__ in, const float* __restrict__ w,
                             const float* __restrict__ b,
                             __nv_bfloat16* __restrict__ hi, __nv_bfloat16* __restrict__ lo) {
    int row = blockIdx.x, tid = threadIdx.x;
    float4 v = ((const float4*)(in + (size_t)row * DM))[tid];
    float s  = v.x + v.y + v.z + v.w;
    float sq = v.x*v.x + v.y*v.y + v.z*v.z + v.w*v.w;
    float tot   = block_reduce_256(s);
    float totsq = block_reduce_256(sq);
    float mean = tot * (1.f / DM);
    float var  = totsq * (1.f / DM) - mean * mean;
    float inv  = rsqrtf(var + EPS_);
    float4 wv = ((const float4*)w)[tid];
    float4 bv = ((const float4*)b)[tid];
    float4 o;
    o.x = (v.x - mean) * inv * wv.x + bv.x;
    o.y = (v.y - mean) * inv * wv.y + bv.y;
    o.z = (v.z - mean) * inv * wv.z + bv.z;
    o.w = (v.w - mean) * inv * wv.w + bv.w;
    u32 h0, l0, h1, l1;
    split2(o.x, o.y, h0, l0);
    split2(o.z, o.w, h1, l1);
    ((uint2*)(hi + (size_t)row * DM))[tid] = make_uint2(h0, h1);
    ((uint2*)(lo + (size_t)row * DM))[tid] = make_uint2(l0, l1);
}

// ---------------- conv4 + silu ----------------
__global__ void conv_kernel(const float* __restrict__ zx, const float* __restrict__ w,
                            const float* __restrict__ bias, float* __restrict__ out) {
    int idx = blockIdx.x * blockDim.x + threadIdx.x;
    if (idx >= TT * CONVD) return;
    int c = idx % CONVD;
    int tt = idx / CONVD;
    int l = tt % L_;
    float acc = bias[c];
    #pragma unroll
    for (int k = 0; k < 4; k++) {
        int ls = l - 3 + k;
        if (ls >= 0)
            acc += zx[(size_t)(tt - 3 + k) * DPROJ + DI + c] * w[c * 4 + k];
    }
    out[idx] = silu_f(acc);
}

// ---------------- dt softplus ----------------
__global__ void dt_kernel(const float* __restrict__ zx, const float* __restrict__ dtb,
                          float* __restrict__ dt) {
    int idx = blockIdx.x * blockDim.x + threadIdx.x;
    if (idx >= TT * NH) return;
    int h = idx % NH;
    float v = zx[(size_t)(idx / NH) * DPROJ + DI + CONVD + h] + dtb[h];
    dt[idx] = (v > 20.f) ? v : log1pf(expf(v));
}

// ---------------- selective scan ----------------
#define CH 8
__global__ void __launch_bounds__(128)
scan_kernel(const float* __restrict__ xbc, const float* __restrict__ dtg,
            const float* __restrict__ A_log, const float* __restrict__ Dp,
            float* __restrict__ y) {
    int blk  = blockIdx.x;
    int half = blk & 1;
    int bh   = blk >> 1;
    int b = bh / NH, h = bh % NH;
    int tid = threadIdx.x;
    int pl  = tid >> 2;
    int q   = tid & 3;
    int p   = half * 32 + pl;

    float Aneg = -expf(A_log[h]);
    float Dh   = Dp[h];

    __shared__ float sB[CH][DS], sC[CH][DS], sx[CH][32], sdt[CH];

    float hreg[16];
    #pragma unroll
    for (int i = 0; i < 16; i++) hreg[i] = 0.f;

    const float* base = xbc + (size_t)b * L_ * CONVD;

    for (int t0 = 0; t0 < L_; t0 += CH) {
        #pragma unroll
        for (int tt = 0; tt < CH; tt++) {
            int tq = t0 + tt;
            const float* rowp = base + (size_t)tq * CONVD;
            if (tid < 64) sB[tt][tid]      = rowp[DI + tid];
            else          sC[tt][tid - 64] = rowp[DI + DS + (tid - 64)];
        }
        #pragma unroll
        for (int tt = 0; tt < CH; tt++) {
            int tq = t0 + tt;
            if (tid < 32)       sx[tt][tid] = base[(size_t)tq * CONVD + h * HD + half * 32 + tid];
            else if (tid == 32) sdt[tt]     = dtg[((size_t)b * L_ + tq) * NH + h];
        }
        __syncthreads();

        #pragma unroll
        for (int tt = 0; tt < CH; tt++) {
            float dtv = sdt[tt];
            float dA  = expf(dtv * Aneg);
            float xv  = sx[tt][pl];
            float cb  = dtv * xv;
            float acc = 0.f;
            #pragma unroll
            for (int i = 0; i < 16; i++) {
                int n = q * 16 + i;
                float hv = hreg[i] * dA + cb * sB[tt][n];
                hreg[i] = hv;
                acc += hv * sC[tt][n];
            }
            acc += __shfl_xor_sync(0xffffffffu, acc, 1);
            acc += __shfl_xor_sync(0xffffffffu, acc, 2);
            if (q == 0) {
                int tq = t0 + tt;
                y[((size_t)b * L_ + tq) * DI + h * HD + p] = acc + Dh * xv;
            }
        }
        __syncthreads();
    }
}

// ---------------- gated RMSNorm -> hi/lo bf16 ----------------
__global__ void rmsnorm_bf_kernel(const float* __restrict__ y, const float* __restrict__ zx,
                                  const float* __restrict__ nw,
                                  __nv_bfloat16* __restrict__ hi, __nv_bfloat16* __restrict__ lo) {
    int row = blockIdx.x, tid = threadIdx.x;
    const float* yr = y  + (size_t)row * DI;
    const float* zr = zx + (size_t)row * DPROJ;
    int c0 = tid * 8;
    float4 y0 = *(const float4*)(yr + c0);
    float4 y1 = *(const float4*)(yr + c0 + 4);
    float4 z0 = *(const float4*)(zr + c0);
    float4 z1 = *(const float4*)(zr + c0 + 4);
    float v[8];
    v[0] = y0.x * silu_f(z0.x); v[1] = y0.y * silu_f(z0.y);
    v[2] = y0.z * silu_f(z0.z); v[3] = y0.w * silu_f(z0.w);
    v[4] = y1.x * silu_f(z1.x); v[5] = y1.y * silu_f(z1.y);
    v[6] = y1.z * silu_f(z1.z); v[7] = y1.w * silu_f(z1.w);
    float sq = 0.f;
    #pragma unroll
    for (int i = 0; i < 8; i++) sq += v[i] * v[i];
    float tot = block_reduce_256(sq);
    float scale = rsqrtf(tot * (1.f / DI) + EPS_);
    float4 w0 = *(const float4*)(nw + c0);
    float4 w1 = *(const float4*)(nw + c0 + 4);
    float o[8];
    o[0] = v[0]*scale*w0.x; o[1] = v[1]*scale*w0.y;
    o[2] = v[2]*scale*w0.z; o[3] = v[3]*scale*w0.w;
    o[4] = v[4]*scale*w1.x; o[5] = v[5]*scale*w1.y;
    o[6] = v[6]*scale*w1.z; o[7] = v[7]*scale*w1.w;
    u32 hp[4], lp[4];
    #pragma unroll
    for (int i = 0; i < 4; i++) split2(o[i*2], o[i*2+1], hp[i], lp[i]);
    ((uint2*)(hi + (size_t)row * DI + c0))[0] = make_uint2(hp[0], hp[1]);
    ((uint2*)(hi + (size_t)row * DI + c0))[1] = make_uint2(hp[2], hp[3]);
    ((uint2*)(lo + (size_t)row * DI + c0))[0] = make_uint2(lp[0], lp[1]);
    ((uint2*)(lo + (size_t)row * DI + c0))[1] = make_uint2(lp[2], lp[3]);
}

// ---------------- launch ----------------
extern "C" void kernel_launch(void* const* d_in, const int* in_sizes, int n_in,
                              void* d_out, int out_size) {
    const float* x          = (const float*)d_in[0];
    const float* ln1_w      = (const float*)d_in[1];
    const float* ln1_b      = (const float*)d_in[2];
    const float* in_proj_w  = (const float*)d_in[3];
    const float* conv_w     = (const float*)d_in[4];
    const float* conv_b     = (const float*)d_in[5];
    const float* dt_bias    = (const float*)d_in[6];
    const float* A_log      = (const float*)d_in[7];
    const float* Dv         = (const float*)d_in[8];
    const float* norm_w     = (const float*)d_in[9];
    const float* out_proj_w = (const float*)d_in[10];
    const float* ln2_w      = (const float*)d_in[11];
    const float* ln2_b      = (const float*)d_in[12];
    const float* mlp_w1     = (const float*)d_in[13];
    const float* mlp_b1     = (const float*)d_in[14];
    const float* mlp_w2     = (const float*)d_in[15];
    const float* mlp_b2     = (const float*)d_in[16];
    float* out = (float*)d_out;

    static float *p_zx = 0, *p_xbc = 0, *p_dt = 0, *p_y = 0, *p_x2 = 0;
    static __nv_bfloat16 *p_h1h = 0, *p_h1l, *p_ynh, *p_ynl, *p_h2h, *p_h2l, *p_glh, *p_gll;
    static __nv_bfloat16 *p_wih, *p_wil, *p_woh, *p_wol, *p_w1h, *p_w1l, *p_w2h, *p_w2l;
    if (p_zx == 0) {
        cudaGetSymbolAddress((void**)&p_zx,  g_zx);
        cudaGetSymbolAddress((void**)&p_xbc, g_xbc);
        cudaGetSymbolAddress((void**)&p_dt,  g_dt);
        cudaGetSymbolAddress((void**)&p_y,   g_y);
        cudaGetSymbolAddress((void**)&p_x2,  g_x2);
        cudaGetSymbolAddress((void**)&p_h1h, g_h1h);
        cudaGetSymbolAddress((void**)&p_h1l, g_h1l);
        cudaGetSymbolAddress((void**)&p_ynh, g_ynh);
        cudaGetSymbolAddress((void**)&p_ynl, g_ynl);
        cudaGetSymbolAddress((void**)&p_h2h, g_h2h);
        cudaGetSymbolAddress((void**)&p_h2l, g_h2l);
        cudaGetSymbolAddress((void**)&p_glh, g_glh);
        cudaGetSymbolAddress((void**)&p_gll, g_gll);
        cudaGetSymbolAddress((void**)&p_wih, g_wih);
        cudaGetSymbolAddress((void**)&p_wil, g_wil);
        cudaGetSymbolAddress((void**)&p_woh, g_woh);
        cudaGetSymbolAddress((void**)&p_wol, g_wol);
        cudaGetSymbolAddress((void**)&p_w1h, g_w1h);
        cudaGetSymbolAddress((void**)&p_w1l, g_w1l);
        cudaGetSymbolAddress((void**)&p_w2h, g_w2h);
        cudaGetSymbolAddress((void**)&p_w2l, g_w2l);
        cudaFuncSetAttribute(mm_kernel, cudaFuncAttributeMaxDynamicSharedMemorySize,
                             (int)SMEM_MM);
    }

    dim3 blk512(512, 1, 1);

    // weight splits (memory bound)
    wsplit_kernel<<<(DPROJ * DM / 4 + 255) / 256, 256>>>(in_proj_w, p_wih, p_wil, DPROJ * DM / 4);
    wsplit_kernel<<<(DM * DI / 4 + 255) / 256, 256>>>(out_proj_w, p_woh, p_wol, DM * DI / 4);
    wsplit_kernel<<<(4 * DM * DM / 4 + 255) / 256, 256>>>(mlp_w1, p_w1h, p_w1l, 4 * DM * DM / 4);
    wsplit_kernel<<<(DM * 4 * DM / 4 + 255) / 256, 256>>>(mlp_w2, p_w2h, p_w2l, DM * 4 * DM / 4);

    // 1) LN1 -> hi/lo
    ln_bf_kernel<<<TT, 256>>>(x, ln1_w, ln1_b, p_h1h, p_h1l);

    // 2) in_proj
    dim3 g1((DPROJ + 127) / 128, TT / 128, 1);
    mm_kernel<<<g1, blk512, SMEM_MM>>>(p_h1h, p_h1l, p_wih, p_wil,
                                       (const float*)0, (const float*)0,
                                       p_zx, (__nv_bfloat16*)0, (__nv_bfloat16*)0,
                                       TT, DPROJ, DM, 0);

    // 3) conv + dt
    conv_kernel<<<(TT * CONVD + 255) / 256, 256>>>(p_zx, conv_w, conv_b, p_xbc);
    dt_kernel<<<(TT * NH + 255) / 256, 256>>>(p_zx, dt_bias, p_dt);

    // 4) scan
    scan_kernel<<<B_ * NH * 2, 128>>>(p_xbc, p_dt, A_log, Dv, p_y);

    // 5) gated rmsnorm -> hi/lo
    rmsnorm_bf_kernel<<<TT, 256>>>(p_y, p_zx, norm_w, p_ynh, p_ynl);

    // 6) out_proj + residual
    dim3 g2(DM / 128, TT / 128, 1);
    mm_kernel<<<g2, blk512, SMEM_MM>>>(p_ynh, p_ynl, p_woh, p_wol,
                                       (const float*)0, x,
                                       p_x2, (__nv_bfloat16*)0, (__nv_bfloat16*)0,
                                       TT, DM, DI, 1);

    // 7) LN2 -> hi/lo
    ln_bf_kernel<<<TT, 256>>>(p_x2, ln2_w, ln2_b, p_h2h, p_h2l);

    // 8) mlp1 + bias + gelu -> hi/lo
    dim3 g3(4 * DM / 128, TT / 128, 1);
    mm_kernel<<<g3, blk512, SMEM_MM>>>(p_h2h, p_h2l, p_w1h, p_w1l,
                                       mlp_b1, (const float*)0,
                                       (float*)0, p_glh, p_gll,
                                       TT, 4 * DM, DM, 2);

    // 9) mlp2 + bias + residual -> out
    dim3 g4(DM / 128, TT / 128, 1);
    mm_kernel<<<g4, blk512, SMEM_MM>>>(p_glh, p_gll, p_w2h, p_w2l,
                                       mlp_b2, p_x2,
                                       out, (__nv_bfloat16*)0, (__nv_bfloat16*)0,
                                       TT, DM, 4 * DM, 3);
}

// round 16
// speedup vs baseline: 1.6596x; 1.0762x over previous
#include <cuda_runtime.h>
#include <cuda_fp16.h>
#include <stdint.h>
#include <math.h>

typedef unsigned int       u32;
typedef unsigned long long u64;

// ---------------- problem constants ----------------
#define B_      2
#define L_      2048
#define DM      1024
#define DI      2048
#define NH      32
#define HD      64
#define DS      64
#define CONVD   2176
#define DPROJ   4256
#define TT      (B_*L_)
#define EPS_    1e-5f
#define WSCALE     32.f
#define INV_WSCALE 0.03125f

// ---------------- scratch ----------------
__device__ float g_zx [TT*DPROJ];
__device__ float g_xbc[TT*CONVD];
__device__ float g_dt [TT*NH];
__device__ float g_y  [TT*DI];
__device__ float g_x2 [TT*DM];

__device__ __half g_h1h[TT*DM];
__device__ __half g_ynh[TT*DI];
__device__ __half g_h2h[TT*DM];
__device__ __half g_glh[TT*4*DM];
__device__ __half g_wih[DPROJ*DM], g_wil[DPROJ*DM];
__device__ __half g_woh[DM*DI],    g_wol[DM*DI];
__device__ __half g_w1h[4*DM*DM],  g_w1l[4*DM*DM];
__device__ __half g_w2h[DM*4*DM],  g_w2l[DM*4*DM];

// ---------------- helpers ----------------
__device__ __forceinline__ float block_reduce_256(float v) {
    static __shared__ float sh[8];
    int tid = threadIdx.x;
    #pragma unroll
    for (int o = 16; o > 0; o >>= 1) v += __shfl_xor_sync(0xffffffffu, v, o);
    __syncthreads();
    if ((tid & 31) == 0) sh[tid >> 5] = v;
    __syncthreads();
    return sh[0]+sh[1]+sh[2]+sh[3]+sh[4]+sh[5]+sh[6]+sh[7];
}

__device__ __forceinline__ float silu_f(float x) {
    return x / (1.f + __expf(-x));
}

__device__ __forceinline__ u32 smem_u32(const void* p) {
    u32 a;
    asm("{ .reg .u64 t; cvta.to.shared.u64 t, %1; cvt.u32.u64 %0, t; }" : "=r"(a) : "l"(p));
    return a;
}

__device__ __forceinline__ void ldsm_x4(u32& r0, u32& r1, u32& r2, u32& r3, u32 addr) {
    asm volatile("ldmatrix.sync.aligned.m8n8.x4.shared.b16 {%0,%1,%2,%3}, [%4];"
                 : "=r"(r0), "=r"(r1), "=r"(r2), "=r"(r3) : "r"(addr));
}

__device__ __forceinline__ void sts128(u32 addr, uint4 v) {
    asm volatile("st.shared.v4.b32 [%0], {%1,%2,%3,%4};"
                 :: "r"(addr), "r"(v.x), "r"(v.y), "r"(v.z), "r"(v.w) : "memory");
}

__device__ __forceinline__ void mma_f16(float* d, u32 a0, u32 a1, u32 a2, u32 a3,
                                        u32 b0, u32 b1) {
    asm volatile(
        "mma.sync.aligned.m16n8k16.row.col.f32.f16.f16.f32 "
        "{%0,%1,%2,%3}, {%4,%5,%6,%7}, {%8,%9}, {%0,%1,%2,%3};"
        : "+f"(d[0]), "+f"(d[1]), "+f"(d[2]), "+f"(d[3])
        : "r"(a0), "r"(a1), "r"(a2), "r"(a3), "r"(b0), "r"(b1));
}

// weight split: (w*32) = hi + lo, both fp16 (scale keeps lo out of subnormals)
__device__ __forceinline__ void wsplit2(float x, float y, u32& hi, u32& lo) {
    x *= WSCALE; y *= WSCALE;
    __half hx = __float2half_rn(x);
    __half hy = __float2half_rn(y);
    float rx = x - __half2float(hx);
    float ry = y - __half2float(hy);
    __half lx = __float2half_rn(rx);
    __half ly = __float2half_rn(ry);
    hi = (u32)__half_as_ushort(hx) | ((u32)__half_as_ushort(hy) << 16);
    lo = (u32)__half_as_ushort(lx) | ((u32)__half_as_ushort(ly) << 16);
}

__device__ __forceinline__ u32 pack_h2(float x, float y) {
    __half2 h = __floats2half2_rn(x, y);
    return *(u32*)&h;
}

// ---------------- fp16 2-product HMMA GEMM: C = (A @ (32B)^T) / 32 ----------------
// A single fp16 [M,K]; B weights pre-split hi/lo fp16 (x32), [N,K].
// epi: 0 C fp32; 1 +res; 2 bias+gelu -> Ch fp16; 3 bias+res
#define ROWB   80
#define OFF_BH 10240u
#define OFF_BL 20480u
#define STAGE_SZ 30720u
#define SMEM_MM (3u * STAGE_SZ)   /* 92160 */

__global__ void __launch_bounds__(512)
mm_kernel(const __half* __restrict__ Ah, const __half* __restrict__ Bhi,
          const __half* __restrict__ Blo,
          const float* __restrict__ bias, const float* __restrict__ res,
          float* __restrict__ C, __half* __restrict__ Ch,
          int M, int N, int K, int epi) {
    extern __shared__ char smc[];
    u32 sb = smem_u32(smc);

    int tid = threadIdx.x;
    int wid = tid >> 5, t = tid & 31;
    int bx = blockIdx.x, by = blockIdx.y;
    int wm = wid & 3, wn = wid >> 2;      // 4x4 warp grid, warp tile m32 x n32

    float acc[2][4][4];
    #pragma unroll
    for (int i = 0; i < 2; i++)
        #pragma unroll
        for (int j = 0; j < 4; j++)
            #pragma unroll
            for (int k = 0; k < 4; k++) acc[i][j][k] = 0.f;

    const int nc = K >> 5;

    // each thread owns one 16B chunk of one row per buffer
    int lr = tid >> 2;                 // row 0..127
    int ch = (tid & 3) * 16;           // byte offset within 64B k-slice
    int ga = by * 128 + lr;
    int gb = bx * 128 + lr; if (gb > N - 1) gb = N - 1;
    const char* pA  = (const char*)(Ah  + (size_t)ga * K) + ch;
    const char* pBh = (const char*)(Bhi + (size_t)gb * K) + ch;
    const char* pBl = (const char*)(Blo + (size_t)gb * K) + ch;
    u32 sO = (u32)lr * ROWB + (u32)ch;

    uint4 rg[3];
    auto load_regs = [&](int c) {
        size_t go = (size_t)(c << 6);       // c*32 fp16 = c*64 bytes
        rg[0] = *(const uint4*)(pA  + go);
        rg[1] = *(const uint4*)(pBh + go);
        rg[2] = *(const uint4*)(pBl + go);
    };
    auto store_smem = [&](int s) {
        u32 base = sb + (u32)s * STAGE_SZ + sO;
        sts128(base,          rg[0]);
        sts128(base + OFF_BH, rg[1]);
        sts128(base + OFF_BL, rg[2]);
    };

    // ldmatrix addressing (proven R7/R12/R14)
    u32 arow = (u32)(wm * 32 + (t & 15));
    u32 acol = (u32)((t >> 4) << 4);
    u32 brow = (u32)(wn * 32 + (t & 7) + ((t >> 4) << 3));
    u32 bcol = (u32)(((t >> 3) & 1) << 4);

    auto compute = [&](int s) {
        u32 base = sb + (u32)s * STAGE_SZ;
        #pragma unroll
        for (int ks = 0; ks < 2; ks++) {
            u32 kb = (u32)(ks * 32);
            u32 ah[2][4], bh[2][4], bl[2][4];
            #pragma unroll
            for (int mi = 0; mi < 2; mi++) {
                u32 ad = base + (arow + mi * 16) * ROWB + kb + acol;
                ldsm_x4(ah[mi][0], ah[mi][1], ah[mi][2], ah[mi][3], ad);
            }
            #pragma unroll
            for (int nj = 0; nj < 2; nj++) {
                u32 bd = base + OFF_BH + (brow + nj * 16) * ROWB + kb + bcol;
                ldsm_x4(bh[nj][0], bh[nj][1], bh[nj][2], bh[nj][3], bd);
                ldsm_x4(bl[nj][0], bl[nj][1], bl[nj][2], bl[nj][3], bd + (OFF_BL - OFF_BH));
            }
            #pragma unroll
            for (int mi = 0; mi < 2; mi++) {
                #pragma unroll
                for (int nj = 0; nj < 4; nj++) {
                    u32 b0h = bh[nj >> 1][(nj & 1) * 2], b1h = bh[nj >> 1][(nj & 1) * 2 + 1];
                    u32 b0l = bl[nj >> 1][(nj & 1) * 2], b1l = bl[nj >> 1][(nj & 1) * 2 + 1];
                    mma_f16(acc[mi][nj], ah[mi][0], ah[mi][1], ah[mi][2], ah[mi][3], b0h, b1h);
                    mma_f16(acc[mi][nj], ah[mi][0], ah[mi][1], ah[mi][2], ah[mi][3], b0l, b1l);
                }
            }
        }
    };

    // ---- 3-stage ring, register staging, ONE barrier per iteration ----
    load_regs(0); store_smem(0);
    load_regs(1); store_smem(1);
    __syncthreads();
    int s_cur = 0, s_next = 2;
    for (int c = 0; c < nc; c++) {
        bool pre = (c + 2 < nc);
        if (pre) load_regs(c + 2);
        compute(s_cur);
        if (pre) store_smem(s_next);
        __syncthreads();
        s_cur  = (s_cur  == 2) ? 0 : s_cur  + 1;
        s_next = (s_next == 2) ? 0 : s_next + 1;
    }

    // ---- epilogue (undo x32 weight scale) ----
    int gid = t >> 2, tig = t & 3;
    #pragma unroll
    for (int mi = 0; mi < 2; mi++) {
        int gm0 = by * 128 + wm * 32 + mi * 16 + gid;
        #pragma unroll
        for (int nj = 0; nj < 4; nj++) {
            int gn = bx * 128 + wn * 32 + nj * 8 + tig * 2;
            if (gn >= N) continue;
            #pragma unroll
            for (int h = 0; h < 2; h++) {
                int gr = gm0 + h * 8;
                float vx = acc[mi][nj][h * 2 + 0] * INV_WSCALE;
                float vy = acc[mi][nj][h * 2 + 1] * INV_WSCALE;
                if (epi == 2 || epi == 3) {
                    float2 bv = *(const float2*)(bias + gn);
                    vx += bv.x; vy += bv.y;
                }
                if (epi == 2) {
                    vx = 0.5f * vx * (1.f + erff(vx * 0.70710678118654752f));
                    vy = 0.5f * vy * (1.f + erff(vy * 0.70710678118654752f));
                    *(u32*)(Ch + (size_t)gr * N + gn) = pack_h2(vx, vy);
                } else {
                    if (epi == 1 || epi == 3) {
                        float2 rv = *(const float2*)(res + (size_t)gr * N + gn);
                        vx += rv.x; vy += rv.y;
                    }
                    float2 o; o.x = vx; o.y = vy;
                    *(float2*)(C + (size_t)gr * N + gn) = o;
                }
            }
        }
    }
}

// ---------------- weight split (x32, fp16 hi/lo) ----------------
__global__ void wsplit_kernel(const float* __restrict__ in, __half* __restrict__ hi,
                              __half* __restrict__ lo, int n4) {
    int i = blockIdx.x * blockDim.x + threadIdx.x;
    if (i >= n4) return;
    float4 v = ((const float4*)in)[i];
    u32 h0, l0, h1, l1;
    wsplit2(v.x, v.y, h0, l0);
    wsplit2(v.z, v.w, h1, l1);
    ((uint2*)hi)[i] = make_uint2(h0, h1);
    ((uint2*)lo)[i] = make_uint2(l0, l1);
}

// ---------------- LayerNorm -> fp16 ----------------
__global__ void ln_h_kernel(const float* __restrict__ in, const float* __restrict__ w,
                            const float* __restrict__ b, __half* __restrict__ hi) {
    int row = blockIdx.x, tid = threadIdx.x;
    float4 v = ((const float4*)(in + (size_t)row * DM))[tid];
    float s  = v.x + v.y + v.z + v.w;
    float sq = v.x*v.x + v.y*v.y + v.z*v.z + v.w*v.w;
    float tot   = block_reduce_256(s);
    float totsq = block_reduce_256(sq);
    float mean = tot * (1.f / DM);
    float var  = totsq * (1.f / DM) - mean * mean;
    float inv  = rsqrtf(var + EPS_);
    float4 wv = ((const float4*)w)[tid];
    float4 bv = ((const float4*)b)[tid];
    float4 o;
    o.x = (v.x - mean) * inv * wv.x + bv.x;
    o.y = (v.y - mean) * inv * wv.y + bv.y;
    o.z = (v.z - mean) * inv * wv.z + bv.z;
    o.w = (v.w - mean) * inv * wv.w + bv.w;
    ((uint2*)(hi + (size_t)row * DM))[tid] =
        make_uint2(pack_h2(o.x, o.y), pack_h2(o.z, o.w));
}

// ---------------- conv4 + silu ----------------
__global__ void conv_kernel(const float* __restrict__ zx, const float* __restrict__ w,
                            const float* __restrict__ bias, float* __restrict__ out) {
    int idx = blockIdx.x * blockDim.x + threadIdx.x;
    if (idx >= TT * CONVD) return;
    int c = idx % CONVD;
    int tt = idx / CONVD;
    int l = tt % L_;
    float acc = bias[c];
    #pragma unroll
    for (int k = 0; k < 4; k++) {
        int ls = l - 3 + k;
        if (ls >= 0)
            acc += zx[(size_t)(tt - 3 + k) * DPROJ + DI + c] * w[c * 4 + k];
    }
    out[idx] = silu_f(acc);
}

// ---------------- dt softplus ----------------
__global__ void dt_kernel(const float* __restrict__ zx, const float* __restrict__ dtb,
                          float* __restrict__ dt) {
    int idx = blockIdx.x * blockDim.x + threadIdx.x;
    if (idx >= TT * NH) return;
    int h = idx % NH;
    float v = zx[(size_t)(idx / NH) * DPROJ + DI + CONVD + h] + dtb[h];
    dt[idx] = (v > 20.f) ? v : log1pf(expf(v));
}

// ---------------- selective scan ----------------
#define CH 8
__global__ void __launch_bounds__(128)
scan_kernel(const float* __restrict__ xbc, const float* __restrict__ dtg,
            const float* __restrict__ A_log, const float* __restrict__ Dp,
            float* __restrict__ y) {
    int blk  = blockIdx.x;
    int half = blk & 1;
    int bh   = blk >> 1;
    int b = bh / NH, h = bh % NH;
    int tid = threadIdx.x;
    int pl  = tid >> 2;
    int q   = tid & 3;
    int p   = half * 32 + pl;

    float Aneg = -expf(A_log[h]);
    float Dh   = Dp[h];

    __shared__ float sB[CH][DS], sC[CH][DS], sx[CH][32], sdt[CH];

    float hreg[16];
    #pragma unroll
    for (int i = 0; i < 16; i++) hreg[i] = 0.f;

    const float* base = xbc + (size_t)b * L_ * CONVD;

    for (int t0 = 0; t0 < L_; t0 += CH) {
        #pragma unroll
        for (int tt = 0; tt < CH; tt++) {
            int tq = t0 + tt;
            const float* rowp = base + (size_t)tq * CONVD;
            if (tid < 64) sB[tt][tid]      = rowp[DI + tid];
            else          sC[tt][tid - 64] = rowp[DI + DS + (tid - 64)];
        }
        #pragma unroll
        for (int tt = 0; tt < CH; tt++) {
            int tq = t0 + tt;
            if (tid < 32)       sx[tt][tid] = base[(size_t)tq * CONVD + h * HD + half * 32 + tid];
            else if (tid == 32) sdt[tt]     = dtg[((size_t)b * L_ + tq) * NH + h];
        }
        __syncthreads();

        #pragma unroll
        for (int tt = 0; tt < CH; tt++) {
            float dtv = sdt[tt];
            float dA  = expf(dtv * Aneg);
            float xv  = sx[tt][pl];
            float cb  = dtv * xv;
            float acc = 0.f;
            #pragma unroll
            for (int i = 0; i < 16; i++) {
                int n = q * 16 + i;
                float hv = hreg[i] * dA + cb * sB[tt][n];
                hreg[i] = hv;
                acc += hv * sC[tt][n];
            }
            acc += __shfl_xor_sync(0xffffffffu, acc, 1);
            acc += __shfl_xor_sync(0xffffffffu, acc, 2);
            if (q == 0) {
                int tq = t0 + tt;
                y[((size_t)b * L_ + tq) * DI + h * HD + p] = acc + Dh * xv;
            }
        }
        __syncthreads();
    }
}

// ---------------- gated RMSNorm -> fp16 ----------------
__global__ void rmsnorm_h_kernel(const float* __restrict__ y, const float* __restrict__ zx,
                                 const float* __restrict__ nw, __half* __restrict__ hi) {
    int row = blockIdx.x, tid = threadIdx.x;
    const float* yr = y  + (size_t)row * DI;
    const float* zr = zx + (size_t)row * DPROJ;
    int c0 = tid * 8;
    float4 y0 = *(const float4*)(yr + c0);
    float4 y1 = *(const float4*)(yr + c0 + 4);
    float4 z0 = *(const float4*)(zr + c0);
    float4 z1 = *(const float4*)(zr + c0 + 4);
    float v[8];
    v[0] = y0.x * silu_f(z0.x); v[1] = y0.y * silu_f(z0.y);
    v[2] = y0.z * silu_f(z0.z); v[3] = y0.w * silu_f(z0.w);
    v[4] = y1.x * silu_f(z1.x); v[5] = y1.y * silu_f(z1.y);
    v[6] = y1.z * silu_f(z1.z); v[7] = y1.w * silu_f(z1.w);
    float sq = 0.f;
    #pragma unroll
    for (int i = 0; i < 8; i++) sq += v[i] * v[i];
    float tot = block_reduce_256(sq);
    float scale = rsqrtf(tot * (1.f / DI) + EPS_);
    float4 w0 = *(const float4*)(nw + c0);
    float4 w1 = *(const float4*)(nw + c0 + 4);
    uint4 o;
    o.x = pack_h2(v[0]*scale*w0.x, v[1]*scale*w0.y);
    o.y = pack_h2(v[2]*scale*w0.z, v[3]*scale*w0.w);
    o.z = pack_h2(v[4]*scale*w1.x, v[5]*scale*w1.y);
    o.w = pack_h2(v[6]*scale*w1.z, v[7]*scale*w1.w);
    *(uint4*)(hi + (size_t)row * DI + c0) = o;
}

// ---------------- launch ----------------
extern "C" void kernel_launch(void* const* d_in, const int* in_sizes, int n_in,
                              void* d_out, int out_size) {
    const float* x          = (const float*)d_in[0];
    const float* ln1_w      = (const float*)d_in[1];
    const float* ln1_b      = (const float*)d_in[2];
    const float* in_proj_w  = (const float*)d_in[3];
    const float* conv_w     = (const float*)d_in[4];
    const float* conv_b     = (const float*)d_in[5];
    const float* dt_bias    = (const float*)d_in[6];
    const float* A_log      = (const float*)d_in[7];
    const float* Dv         = (const float*)d_in[8];
    const float* norm_w     = (const float*)d_in[9];
    const float* out_proj_w = (const float*)d_in[10];
    const float* ln2_w      = (const float*)d_in[11];
    const float* ln2_b      = (const float*)d_in[12];
    const float* mlp_w1     = (const float*)d_in[13];
    const float* mlp_b1     = (const float*)d_in[14];
    const float* mlp_w2     = (const float*)d_in[15];
    const float* mlp_b2     = (const float*)d_in[16];
    float* out = (float*)d_out;

    static float *p_zx = 0, *p_xbc = 0, *p_dt = 0, *p_y = 0, *p_x2 = 0;
    static __half *p_h1h = 0, *p_ynh, *p_h2h, *p_glh;
    static __half *p_wih, *p_wil, *p_woh, *p_wol, *p_w1h, *p_w1l, *p_w2h, *p_w2l;
    if (p_zx == 0) {
        cudaGetSymbolAddress((void**)&p_zx,  g_zx);
        cudaGetSymbolAddress((void**)&p_xbc, g_xbc);
        cudaGetSymbolAddress((void**)&p_dt,  g_dt);
        cudaGetSymbolAddress((void**)&p_y,   g_y);
        cudaGetSymbolAddress((void**)&p_x2,  g_x2);
        cudaGetSymbolAddress((void**)&p_h1h, g_h1h);
        cudaGetSymbolAddress((void**)&p_ynh, g_ynh);
        cudaGetSymbolAddress((void**)&p_h2h, g_h2h);
        cudaGetSymbolAddress((void**)&p_glh, g_glh);
        cudaGetSymbolAddress((void**)&p_wih, g_wih);
        cudaGetSymbolAddress((void**)&p_wil, g_wil);
        cudaGetSymbolAddress((void**)&p_woh, g_woh);
        cudaGetSymbolAddress((void**)&p_wol, g_wol);
        cudaGetSymbolAddress((void**)&p_w1h, g_w1h);
        cudaGetSymbolAddress((void**)&p_w1l, g_w1l);
        cudaGetSymbolAddress((void**)&p_w2h, g_w2h);
        cudaGetSymbolAddress((void**)&p_w2l, g_w2l);
        cudaFuncSetAttribute(mm_kernel, cudaFuncAttributeMaxDynamicSharedMemorySize,
                             (int)SMEM_MM);
    }

    dim3 blk512(512, 1, 1);

    // weight splits (memory bound)
    wsplit_kernel<<<(DPROJ * DM / 4 + 255) / 256, 256>>>(in_proj_w, p_wih, p_wil, DPROJ * DM / 4);
    wsplit_kernel<<<(DM * DI / 4 + 255) / 256, 256>>>(out_proj_w, p_woh, p_wol, DM * DI / 4);
    wsplit_kernel<<<(4 * DM * DM / 4 + 255) / 256, 256>>>(mlp_w1, p_w1h, p_w1l, 4 * DM * DM / 4);
    wsplit_kernel<<<(DM * 4 * DM / 4 + 255) / 256, 256>>>(mlp_w2, p_w2h, p_w2l, DM * 4 * DM / 4);

    // 1) LN1 -> fp16
    ln_h_kernel<<<TT, 256>>>(x, ln1_w, ln1_b, p_h1h);

    // 2) in_proj
    dim3 g1((DPROJ + 127) / 128, TT / 128, 1);
    mm_kernel<<<g1, blk512, SMEM_MM>>>(p_h1h, p_wih, p_wil,
                                       (const float*)0, (const float*)0,
                                       p_zx, (__half*)0,
                                       TT, DPROJ, DM, 0);

    // 3) conv + dt
    conv_kernel<<<(TT * CONVD + 255) / 256, 256>>>(p_zx, conv_w, conv_b, p_xbc);
    dt_kernel<<<(TT * NH + 255) / 256, 256>>>(p_zx, dt_bias, p_dt);

    // 4) scan
    scan_kernel<<<B_ * NH * 2, 128>>>(p_xbc, p_dt, A_log, Dv, p_y);

    // 5) gated rmsnorm -> fp16
    rmsnorm_h_kernel<<<TT, 256>>>(p_y, p_zx, norm_w, p_ynh);

    // 6) out_proj + residual
    dim3 g2(DM / 128, TT / 128, 1);
    mm_kernel<<<g2, blk512, SMEM_MM>>>(p_ynh, p_woh, p_wol,
                                       (const float*)0, x,
                                       p_x2, (__half*)0,
                                       TT, DM, DI, 1);

    // 7) LN2 -> fp16
    ln_h_kernel<<<TT, 256>>>(p_x2, ln2_w, ln2_b, p_h2h);

    // 8) mlp1 + bias + gelu -> fp16
    dim3 g3(4 * DM / 128, TT / 128, 1);
    mm_kernel<<<g3, blk512, SMEM_MM>>>(p_h2h, p_w1h, p_w1l,
                                       mlp_b1, (const float*)0,
                                       (float*)0, p_glh,
                                       TT, 4 * DM, DM, 2);

    // 9) mlp2 + bias + residual -> out
    dim3 g4(DM / 128, TT / 128, 1);
    mm_kernel<<<g4, blk512, SMEM_MM>>>(p_glh, p_w2h, p_w2l,
                                       mlp_b2, p_x2,
                                       out, (__half*)0,
                                       TT, DM, 4 * DM, 3);
}